// round 2
// baseline (speedup 1.0000x reference)
#include <cuda_runtime.h>
#include <math.h>

#define N_NODES 50000
#define N_EDGES 800000
#define D 128

// ---------------- scratch (device globals; re-initialized every launch) ----
__device__ float g_xT [(size_t)N_NODES * D];   // X transposed: [N,128]
__device__ float g_xw [(size_t)N_NODES * D];   // GEMM output (per layer)
__device__ float g_msg[(size_t)N_NODES * D];   // edge aggregation accumulator
__device__ float g_f1 [(size_t)N_NODES * D];   // layer-1 output
__device__ float g_y  [(size_t)N_NODES * D];   // layer-2 output + residual
__device__ float g_deg[N_NODES];               // degree, then dinv = rsqrt(deg)
__device__ float g_cs [D];                     // column sum of y
__device__ float g_cs2[D];                     // column sum of y^2

__device__ __forceinline__ float gelu_exact(float v) {
    // jax.nn.gelu(approximate=False) = x * Phi(x)
    return v * normcdff(v);
}

// ---------------- init: deg=1 (self loop), zero column stats ---------------
__global__ void k_init() {
    int i = blockIdx.x * blockDim.x + threadIdx.x;
    if (i < N_NODES) g_deg[i] = 1.0f;
    if (i < D) { g_cs[i] = 0.0f; g_cs2[i] = 0.0f; }
}

// ---------------- degree count over edge dst (edge_index is INT32) ---------
__global__ void k_deg(const int* __restrict__ ei) {
    int e = blockIdx.x * blockDim.x + threadIdx.x;
    if (e < N_EDGES) {
        int d = ei[N_EDGES + e];
        atomicAdd(&g_deg[d], 1.0f);
    }
}

__global__ void k_rsqrt() {
    int i = blockIdx.x * blockDim.x + threadIdx.x;
    if (i < N_NODES) g_deg[i] = rsqrtf(g_deg[i]);
}

// ---------------- transpose X [128,N] -> xT [N,128] ------------------------
__global__ void k_transpose(const float* __restrict__ X) {
    __shared__ float s[32][33];
    int n0 = blockIdx.x * 32;
    int f0 = blockIdx.y * 32;
    int tx = threadIdx.x, ty = threadIdx.y;
    int n = n0 + tx;
    int f = f0 + ty;                    // f always < 128
    if (n < N_NODES) s[ty][tx] = X[(size_t)f * N_NODES + n];
    __syncthreads();
    int n2 = n0 + ty;
    int f2 = f0 + tx;
    if (n2 < N_NODES) g_xT[(size_t)n2 * D + f2] = s[tx][ty];
}

// ---------------- zero the msg accumulator ---------------------------------
__global__ void k_zero_msg() {
    for (size_t i = (size_t)blockIdx.x * blockDim.x + threadIdx.x;
         i < (size_t)N_NODES * D; i += (size_t)gridDim.x * blockDim.x)
        g_msg[i] = 0.0f;
}

// ---------------- GEMM: Out[n,j] = sum_f A[n,f] * W[f,j] -------------------
// A row-major [N,128], W row-major [128,128], Out = g_xw.
// Block: 64 nodes x 128 cols, 256 threads, 32 accumulators / thread.
__global__ void k_gemm(int src_sel, const float* __restrict__ W) {
    const float* __restrict__ A = src_sel ? g_f1 : g_xT;
    __shared__ float As[64][17];    // 16-f chunk, padded (17 odd -> no conflict)
    __shared__ float Ws[16][128];
    int t = threadIdx.x;
    int nl = t & 63;                // node within tile
    int jg = (t >> 6) << 5;         // 32-column group
    int nbase = blockIdx.x * 64;
    int node = nbase + nl;

    float acc[32];
#pragma unroll
    for (int j = 0; j < 32; j++) acc[j] = 0.0f;

    for (int fc = 0; fc < D; fc += 16) {
#pragma unroll
        for (int k = 0; k < 4; k++) {           // 64x16 A chunk
            int idx = t + k * 256;
            int r = idx >> 4, c = idx & 15;
            int n = nbase + r;
            As[r][c] = (n < N_NODES) ? A[(size_t)n * D + fc + c] : 0.0f;
        }
#pragma unroll
        for (int k = 0; k < 8; k++) {           // 16x128 W chunk
            int idx = t + k * 256;
            int r = idx >> 7, c = idx & 127;
            Ws[r][c] = W[(fc + r) * D + c];
        }
        __syncthreads();
#pragma unroll
        for (int ff = 0; ff < 16; ff++) {
            float a = As[nl][ff];
#pragma unroll
            for (int jj = 0; jj < 32; jj++)
                acc[jj] += a * Ws[ff][jg + jj];
        }
        __syncthreads();
    }

    if (node < N_NODES) {
        float4* o = (float4*)(g_xw + (size_t)node * D + jg);
#pragma unroll
        for (int q = 0; q < 8; q++)
            o[q] = make_float4(acc[4*q], acc[4*q+1], acc[4*q+2], acc[4*q+3]);
    }
}

// ---------------- edge scatter: msg[dst] += xw[src] * dinv[s]*dinv[d] -------
// One warp per edge; lane handles one float4 (4 features).
__global__ void k_scatter(const int* __restrict__ ei) {
    int gw = (blockIdx.x * blockDim.x + threadIdx.x) >> 5;
    if (gw >= N_EDGES) return;
    int lane = threadIdx.x & 31;
    int s = __ldg(&ei[gw]);
    int d = __ldg(&ei[N_EDGES + gw]);
    float norm = g_deg[s] * g_deg[d];
    float4 v = ((const float4*)(g_xw + (size_t)s * D))[lane];
    float* dst = g_msg + (size_t)d * D + lane * 4;
    atomicAdd(dst + 0, v.x * norm);
    atomicAdd(dst + 1, v.y * norm);
    atomicAdd(dst + 2, v.z * norm);
    atomicAdd(dst + 3, v.w * norm);
}

// ---------------- per-node: self-loop + bias + MessageNorm + GELU ----------
// stage 0: xprev = g_xT, out = g_f1 (no residual)
// stage 1: xprev = g_f1, out = g_y = gelu(...) + g_xT (residual)
__global__ void k_node(int stage, const float* __restrict__ b,
                       const float* __restrict__ scale) {
    int gw = (blockIdx.x * blockDim.x + threadIdx.x) >> 5;
    if (gw >= N_NODES) return;
    int lane = threadIdx.x & 31;
    size_t off = (size_t)gw * D;

    const float* xprev = stage ? g_f1 : g_xT;
    float* out         = stage ? g_y  : g_f1;

    float di = g_deg[gw];
    float sn = di * di;                       // self-loop norm = 1/deg

    float4 m  = ((const float4*)(g_msg + off))[lane];
    float4 sw = ((const float4*)(g_xw  + off))[lane];
    float4 bb = ((const float4*)b)[lane];
    m.x += sw.x * sn + bb.x;
    m.y += sw.y * sn + bb.y;
    m.z += sw.z * sn + bb.z;
    m.w += sw.w * sn + bb.w;

    float4 xv = ((const float4*)(xprev + off))[lane];

    float ms = m.x*m.x + m.y*m.y + m.z*m.z + m.w*m.w;
    float xs = xv.x*xv.x + xv.y*xv.y + xv.z*xv.z + xv.w*xv.w;
#pragma unroll
    for (int o = 16; o; o >>= 1) {
        ms += __shfl_xor_sync(0xFFFFFFFFu, ms, o);
        xs += __shfl_xor_sync(0xFFFFFFFFu, xs, o);
    }
    float coef = scale[0] * sqrtf(xs) / fmaxf(sqrtf(ms), 1e-12f);

    float4 r;
    r.x = gelu_exact(xv.x + coef * m.x);
    r.y = gelu_exact(xv.y + coef * m.y);
    r.z = gelu_exact(xv.z + coef * m.z);
    r.w = gelu_exact(xv.w + coef * m.w);

    if (stage) {
        float4 rv = ((const float4*)(g_xT + off))[lane];
        r.x += rv.x; r.y += rv.y; r.z += rv.z; r.w += rv.w;
    }
    ((float4*)(out + off))[lane] = r;
}

// ---------------- column stats over y: sum, sum of squares ------------------
__global__ void k_colstats() {
    int c = threadIdx.x;                  // 128 threads, one column each
    float s = 0.0f, s2 = 0.0f;
    for (int n = blockIdx.x; n < N_NODES; n += gridDim.x) {
        float v = g_y[(size_t)n * D + c];
        s += v; s2 += v * v;
    }
    atomicAdd(&g_cs[c],  s);
    atomicAdd(&g_cs2[c], s2);
}

// ---------------- finalize: GraphNorm + GELU -------------------------------
__global__ void k_final(const float* __restrict__ gnw,
                        const float* __restrict__ gnb,
                        const float* __restrict__ gnm,
                        float* __restrict__ out) {
    const float invN = 1.0f / (float)N_NODES;
    for (int idx = blockIdx.x * blockDim.x + threadIdx.x;
         idx < N_NODES * D; idx += gridDim.x * blockDim.x) {
        int c = idx & (D - 1);
        float mean = g_cs[c]  * invN;
        float ey2  = g_cs2[c] * invN;
        float msc  = gnm[c];
        float sub  = g_y[idx] - mean * msc;
        // var of (y - mean*msc): E[y^2] - 2*msc*mean^2 + msc^2*mean^2
        float var  = ey2 - 2.0f * msc * mean * mean + msc * msc * mean * mean;
        float o = gnw[c] * sub * rsqrtf(var + 1e-5f) + gnb[c];
        out[idx] = gelu_exact(o);
    }
}

// ---------------- launch ----------------------------------------------------
extern "C" void kernel_launch(void* const* d_in, const int* in_sizes, int n_in,
                              void* d_out, int out_size) {
    const float* X   = (const float*)d_in[0];
    const int*   ei  = (const int*)  d_in[1];     // int32! (JAX x64 disabled)
    const float* W1  = (const float*)d_in[2];
    const float* b1  = (const float*)d_in[3];
    const float* s1  = (const float*)d_in[4];
    const float* W2  = (const float*)d_in[5];
    const float* b2  = (const float*)d_in[6];
    const float* s2  = (const float*)d_in[7];
    const float* gnw = (const float*)d_in[8];
    const float* gnb = (const float*)d_in[9];
    const float* gnm = (const float*)d_in[10];
    float* out = (float*)d_out;

    const int TB = 256;
    // degrees / norms
    k_init  <<<(N_NODES + TB - 1) / TB, TB>>>();
    k_deg   <<<(N_EDGES + TB - 1) / TB, TB>>>(ei);
    k_rsqrt <<<(N_NODES + TB - 1) / TB, TB>>>();

    // xT = X.T
    dim3 tg((N_NODES + 31) / 32, D / 32);
    k_transpose<<<tg, dim3(32, 32)>>>(X);

    int gemm_blocks    = (N_NODES + 63) / 64;
    int scatter_blocks = (N_EDGES * 32 + TB - 1) / TB;
    int node_blocks    = (N_NODES * 32 + TB - 1) / TB;

    // ---- layer 1 ----
    k_zero_msg<<<4096, TB>>>();
    k_gemm    <<<gemm_blocks, TB>>>(0, W1);
    k_scatter <<<scatter_blocks, TB>>>(ei);
    k_node    <<<node_blocks, TB>>>(0, b1, s1);

    // ---- layer 2 ----
    k_zero_msg<<<4096, TB>>>();
    k_gemm    <<<gemm_blocks, TB>>>(1, W2);
    k_scatter <<<scatter_blocks, TB>>>(ei);
    k_node    <<<node_blocks, TB>>>(1, b2, s2);

    // ---- GraphNorm + GELU ----
    k_colstats<<<512, D>>>();
    k_final   <<<4096, TB>>>(gnw, gnb, gnm, out);
}

// round 3
// speedup vs baseline: 1.5617x; 1.5617x over previous
#include <cuda_runtime.h>
#include <math.h>

#define N_NODES 50000
#define N_EDGES 800000
#define D 128

// ---------------- scratch (device globals; re-initialized every launch) ----
__device__ float g_xT [(size_t)N_NODES * D];   // X transposed: [N,128]
__device__ float g_xw [(size_t)N_NODES * D];   // GEMM out, pre-scaled by dinv[n]
__device__ float g_msg[(size_t)N_NODES * D];   // msg accumulator (init: selfloop+bias)
__device__ float g_f1 [(size_t)N_NODES * D];   // layer-1 output
__device__ float g_y  [(size_t)N_NODES * D];   // layer-2 output + residual
__device__ float g_deg[N_NODES];               // degree -> dinv = rsqrt(deg)
__device__ float g_cs [D];                     // column sum of y
__device__ float g_cs2[D];                     // column sum of y^2

__device__ __forceinline__ float gelu_exact(float v) {
    return v * normcdff(v);     // jax.nn.gelu(approximate=False)
}

// ---------------- init: deg=1 (self loop), zero column stats ---------------
__global__ void k_init() {
    int i = blockIdx.x * blockDim.x + threadIdx.x;
    if (i < N_NODES) g_deg[i] = 1.0f;
    if (i < D) { g_cs[i] = 0.0f; g_cs2[i] = 0.0f; }
}

// ---------------- degree count over edge dst (edge_index is INT32) ---------
__global__ void k_deg(const int* __restrict__ ei) {
    int e = blockIdx.x * blockDim.x + threadIdx.x;
    if (e < N_EDGES) atomicAdd(&g_deg[ei[N_EDGES + e]], 1.0f);
}

__global__ void k_rsqrt() {
    int i = blockIdx.x * blockDim.x + threadIdx.x;
    if (i < N_NODES) g_deg[i] = rsqrtf(g_deg[i]);
}

// ---------------- transpose X [128,N] -> xT [N,128] ------------------------
__global__ void k_transpose(const float* __restrict__ X) {
    __shared__ float s[32][33];
    int n0 = blockIdx.x * 32;
    int f0 = blockIdx.y * 32;
    int tx = threadIdx.x, ty = threadIdx.y;          // (32, 8)
    int n = n0 + tx;
#pragma unroll
    for (int i = 0; i < 4; i++) {
        int f = f0 + ty + i * 8;
        if (n < N_NODES) s[ty + i * 8][tx] = X[(size_t)f * N_NODES + n];
    }
    __syncthreads();
#pragma unroll
    for (int i = 0; i < 4; i++) {
        int n2 = n0 + ty + i * 8;
        int f2 = f0 + tx;
        if (n2 < N_NODES) g_xT[(size_t)n2 * D + f2] = s[tx][ty + i * 8];
    }
}

// ---------------- GEMM + fused epilogue ------------------------------------
// Out[n,j] = sum_f A[n,f] * W[f,j]
// Epilogue: g_xw[n,j]  = out * dinv[n]          (pre-scaled for scatter)
//           g_msg[n,j] = out * dinv[n]^2 + b[j] (self-loop + bias init)
// Block: 64 nodes x 128 cols, 256 threads, each thread 4 nodes x 8 cols.
__global__ void k_gemm(int src_sel, const float* __restrict__ W,
                       const float* __restrict__ bias) {
    const float* __restrict__ A = src_sel ? g_f1 : g_xT;
    __shared__ float As[64][17];
    __shared__ float Ws[16][132];      // padded row (528B, 16B-divisible)
    int t = threadIdx.x;
    int tx = t & 15;                   // column group (8 cols)
    int ty = t >> 4;                   // node group (4 nodes)
    int nbase = blockIdx.x * 64;

    float acc[4][8];
#pragma unroll
    for (int i = 0; i < 4; i++)
#pragma unroll
        for (int j = 0; j < 8; j++) acc[i][j] = 0.0f;

    for (int fc = 0; fc < D; fc += 16) {
#pragma unroll
        for (int k = 0; k < 4; k++) {           // 64x16 A chunk
            int idx = t + k * 256;
            int r = idx >> 4, c = idx & 15;
            int n = nbase + r;
            As[r][c] = (n < N_NODES) ? A[(size_t)n * D + fc + c] : 0.0f;
        }
#pragma unroll
        for (int k = 0; k < 8; k++) {           // 16x128 W chunk
            int idx = t + k * 256;
            int r = idx >> 7, c = idx & 127;
            Ws[r][c] = W[(fc + r) * D + c];
        }
        __syncthreads();
#pragma unroll
        for (int ff = 0; ff < 16; ff++) {
            const float4* wrow = (const float4*)&Ws[ff][0];
            float4 wa = wrow[tx * 2];
            float4 wb = wrow[tx * 2 + 1];
            float w[8] = {wa.x, wa.y, wa.z, wa.w, wb.x, wb.y, wb.z, wb.w};
#pragma unroll
            for (int i = 0; i < 4; i++) {
                float a = As[ty * 4 + i][ff];
#pragma unroll
                for (int j = 0; j < 8; j++)
                    acc[i][j] += a * w[j];
            }
        }
        __syncthreads();
    }

    float4 b0 = ((const float4*)bias)[tx * 2];
    float4 b1 = ((const float4*)bias)[tx * 2 + 1];
#pragma unroll
    for (int i = 0; i < 4; i++) {
        int node = nbase + ty * 4 + i;
        if (node >= N_NODES) continue;
        float di = g_deg[node];
        float sn = di * di;
        size_t off = (size_t)node * D + tx * 8;
        float4 xa = make_float4(acc[i][0]*di, acc[i][1]*di, acc[i][2]*di, acc[i][3]*di);
        float4 xb = make_float4(acc[i][4]*di, acc[i][5]*di, acc[i][6]*di, acc[i][7]*di);
        ((float4*)(g_xw + off))[0] = xa;
        ((float4*)(g_xw + off))[1] = xb;
        float4 ma = make_float4(acc[i][0]*sn + b0.x, acc[i][1]*sn + b0.y,
                                acc[i][2]*sn + b0.z, acc[i][3]*sn + b0.w);
        float4 mb = make_float4(acc[i][4]*sn + b1.x, acc[i][5]*sn + b1.y,
                                acc[i][6]*sn + b1.z, acc[i][7]*sn + b1.w);
        ((float4*)(g_msg + off))[0] = ma;
        ((float4*)(g_msg + off))[1] = mb;
    }
}

// ---------------- edge scatter: msg[dst] += xw[src] * dinv[d] ---------------
// xw already pre-scaled by dinv[src]. One warp per edge; one float4 atomic/lane.
__global__ void k_scatter(const int* __restrict__ ei) {
    int gw = (blockIdx.x * blockDim.x + threadIdx.x) >> 5;
    if (gw >= N_EDGES) return;
    int lane = threadIdx.x & 31;
    int s = __ldg(&ei[gw]);
    int d = __ldg(&ei[N_EDGES + gw]);
    float nd = __ldg(&g_deg[d]);
    float4 v = ((const float4*)(g_xw + (size_t)s * D))[lane];
    v.x *= nd; v.y *= nd; v.z *= nd; v.w *= nd;
    atomicAdd((float4*)(g_msg + (size_t)d * D) + lane, v);
}

// ---------------- per-node: MessageNorm + GELU (+ residual stage 1) --------
__global__ void k_node(int stage, const float* __restrict__ scale) {
    int gw = (blockIdx.x * blockDim.x + threadIdx.x) >> 5;
    if (gw >= N_NODES) return;
    int lane = threadIdx.x & 31;
    size_t off = (size_t)gw * D;

    const float* xprev = stage ? g_f1 : g_xT;
    float* out         = stage ? g_y  : g_f1;

    float4 m  = ((const float4*)(g_msg + off))[lane];
    float4 xv = ((const float4*)(xprev + off))[lane];

    float ms = m.x*m.x + m.y*m.y + m.z*m.z + m.w*m.w;
    float xs = xv.x*xv.x + xv.y*xv.y + xv.z*xv.z + xv.w*xv.w;
#pragma unroll
    for (int o = 16; o; o >>= 1) {
        ms += __shfl_xor_sync(0xFFFFFFFFu, ms, o);
        xs += __shfl_xor_sync(0xFFFFFFFFu, xs, o);
    }
    float coef = scale[0] * sqrtf(xs) / fmaxf(sqrtf(ms), 1e-12f);

    float4 r;
    r.x = gelu_exact(xv.x + coef * m.x);
    r.y = gelu_exact(xv.y + coef * m.y);
    r.z = gelu_exact(xv.z + coef * m.z);
    r.w = gelu_exact(xv.w + coef * m.w);

    if (stage) {
        float4 rv = ((const float4*)(g_xT + off))[lane];
        r.x += rv.x; r.y += rv.y; r.z += rv.z; r.w += rv.w;
    }
    ((float4*)(out + off))[lane] = r;
}

// ---------------- column stats over y ---------------------------------------
__global__ void k_colstats() {
    int c = threadIdx.x;
    float s = 0.0f, s2 = 0.0f;
    for (int n = blockIdx.x; n < N_NODES; n += gridDim.x) {
        float v = g_y[(size_t)n * D + c];
        s += v; s2 += v * v;
    }
    atomicAdd(&g_cs[c],  s);
    atomicAdd(&g_cs2[c], s2);
}

// ---------------- finalize: GraphNorm + GELU -------------------------------
__global__ void k_final(const float* __restrict__ gnw,
                        const float* __restrict__ gnb,
                        const float* __restrict__ gnm,
                        float* __restrict__ out) {
    const float invN = 1.0f / (float)N_NODES;
    for (int idx = blockIdx.x * blockDim.x + threadIdx.x;
         idx < N_NODES * D; idx += gridDim.x * blockDim.x) {
        int c = idx & (D - 1);
        float mean = g_cs[c]  * invN;
        float ey2  = g_cs2[c] * invN;
        float msc  = gnm[c];
        float sub  = g_y[idx] - mean * msc;
        float var  = ey2 - 2.0f * msc * mean * mean + msc * msc * mean * mean;
        float o = gnw[c] * sub * rsqrtf(var + 1e-5f) + gnb[c];
        out[idx] = gelu_exact(o);
    }
}

// ---------------- launch ----------------------------------------------------
extern "C" void kernel_launch(void* const* d_in, const int* in_sizes, int n_in,
                              void* d_out, int out_size) {
    const float* X   = (const float*)d_in[0];
    const int*   ei  = (const int*)  d_in[1];     // int32 (JAX x64 disabled)
    const float* W1  = (const float*)d_in[2];
    const float* b1  = (const float*)d_in[3];
    const float* s1  = (const float*)d_in[4];
    const float* W2  = (const float*)d_in[5];
    const float* b2  = (const float*)d_in[6];
    const float* s2  = (const float*)d_in[7];
    const float* gnw = (const float*)d_in[8];
    const float* gnb = (const float*)d_in[9];
    const float* gnm = (const float*)d_in[10];
    float* out = (float*)d_out;

    const int TB = 256;
    k_init  <<<(N_NODES + TB - 1) / TB, TB>>>();
    k_deg   <<<(N_EDGES + TB - 1) / TB, TB>>>(ei);
    k_rsqrt <<<(N_NODES + TB - 1) / TB, TB>>>();

    dim3 tg((N_NODES + 31) / 32, D / 32);
    k_transpose<<<tg, dim3(32, 8)>>>(X);

    int gemm_blocks    = (N_NODES + 63) / 64;
    int scatter_blocks = (N_EDGES * 32 + TB - 1) / TB;
    int node_blocks    = (N_NODES * 32 + TB - 1) / TB;

    // ---- layer 1 ----
    k_gemm    <<<gemm_blocks, TB>>>(0, W1, b1);
    k_scatter <<<scatter_blocks, TB>>>(ei);
    k_node    <<<node_blocks, TB>>>(0, s1);

    // ---- layer 2 ----
    k_gemm    <<<gemm_blocks, TB>>>(1, W2, b2);
    k_scatter <<<scatter_blocks, TB>>>(ei);
    k_node    <<<node_blocks, TB>>>(1, s2);

    // ---- GraphNorm + GELU ----
    k_colstats<<<512, D>>>();
    k_final   <<<4096, TB>>>(gnw, gnb, gnm, out);
}

// round 4
// speedup vs baseline: 2.2008x; 1.4093x over previous
#include <cuda_runtime.h>
#include <math.h>

#define N_NODES 50000
#define N_EDGES 800000
#define D 128
#define SCAN_B 1024
#define N_SBLK ((N_NODES + SCAN_B - 1) / SCAN_B)   // 49

// ---------------- scratch (device globals; re-initialized every launch) ----
__device__ float g_xT [(size_t)N_NODES * D];   // X transposed: [N,128]
__device__ float g_xw [(size_t)N_NODES * D];   // GEMM out, pre-scaled by dinv[n]
__device__ float g_f1 [(size_t)N_NODES * D];   // layer-1 output
__device__ float g_y  [(size_t)N_NODES * D];   // layer-2 output (+residual)
__device__ float g_deg[N_NODES];               // dinv = rsqrt(1 + in_deg)
__device__ int   g_hist[N_NODES];              // in-degree (no self loop)
__device__ int   g_rowstart[N_NODES];          // CSR row starts (by dst)
__device__ int   g_cursor[N_NODES];            // fill cursors
__device__ int   g_csrc[N_EDGES];              // CSR src indices
__device__ int   g_bsum[64];                   // scan block sums
__device__ float g_cs [D];                     // column sum of y
__device__ float g_cs2[D];                     // column sum of y^2

__device__ __forceinline__ float gelu_exact(float v) {
    return v * normcdff(v);     // jax.nn.gelu(approximate=False)
}

// ---------------- init ------------------------------------------------------
__global__ void k_init() {
    int i = blockIdx.x * blockDim.x + threadIdx.x;
    if (i < N_NODES) g_hist[i] = 0;
    if (i < D) { g_cs[i] = 0.0f; g_cs2[i] = 0.0f; }
}

// ---------------- in-degree histogram (edge_index is INT32) ----------------
__global__ void k_deg(const int* __restrict__ ei) {
    int e = blockIdx.x * blockDim.x + threadIdx.x;
    if (e < N_EDGES) atomicAdd(&g_hist[ei[N_EDGES + e]], 1);
}

__global__ void k_rsqrt() {
    int i = blockIdx.x * blockDim.x + threadIdx.x;
    if (i < N_NODES) g_deg[i] = rsqrtf((float)g_hist[i] + 1.0f);
}

// ---------------- prefix scan of g_hist -> g_rowstart (exclusive) ----------
__global__ void k_scan1() {
    __shared__ int sh[SCAN_B];
    int t = threadIdx.x;
    int i = blockIdx.x * SCAN_B + t;
    int v = (i < N_NODES) ? g_hist[i] : 0;
    sh[t] = v;
    __syncthreads();
    for (int off = 1; off < SCAN_B; off <<= 1) {
        int x = (t >= off) ? sh[t - off] : 0;
        __syncthreads();
        sh[t] += x;
        __syncthreads();
    }
    if (i < N_NODES) g_rowstart[i] = sh[t] - v;      // exclusive within block
    if (t == SCAN_B - 1) g_bsum[blockIdx.x] = sh[t]; // block total
}

__global__ void k_scan2() {     // single block, 64 threads
    __shared__ int sh[64];
    int t = threadIdx.x;
    int v = (t < N_SBLK) ? g_bsum[t] : 0;
    sh[t] = v;
    __syncthreads();
    for (int off = 1; off < 64; off <<= 1) {
        int x = (t >= off) ? sh[t - off] : 0;
        __syncthreads();
        sh[t] += x;
        __syncthreads();
    }
    g_bsum[t] = sh[t] - v;      // exclusive block offsets
}

__global__ void k_scan3() {
    int i = blockIdx.x * blockDim.x + threadIdx.x;
    if (i < N_NODES) {
        int rs = g_rowstart[i] + g_bsum[i / SCAN_B];
        g_rowstart[i] = rs;
        g_cursor[i]   = rs;
    }
}

// ---------------- CSR fill ---------------------------------------------------
__global__ void k_fill(const int* __restrict__ ei) {
    int e = blockIdx.x * blockDim.x + threadIdx.x;
    if (e < N_EDGES) {
        int s = ei[e];
        int d = ei[N_EDGES + e];
        int pos = atomicAdd(&g_cursor[d], 1);
        g_csrc[pos] = s;
    }
}

// ---------------- transpose X [128,N] -> xT [N,128] ------------------------
__global__ void k_transpose(const float* __restrict__ X) {
    __shared__ float s[32][33];
    int n0 = blockIdx.x * 32;
    int f0 = blockIdx.y * 32;
    int tx = threadIdx.x, ty = threadIdx.y;          // (32, 8)
    int n = n0 + tx;
#pragma unroll
    for (int i = 0; i < 4; i++) {
        int f = f0 + ty + i * 8;
        if (n < N_NODES) s[ty + i * 8][tx] = X[(size_t)f * N_NODES + n];
    }
    __syncthreads();
#pragma unroll
    for (int i = 0; i < 4; i++) {
        int n2 = n0 + ty + i * 8;
        int f2 = f0 + tx;
        if (n2 < N_NODES) g_xT[(size_t)n2 * D + f2] = s[tx][ty + i * 8];
    }
}

// ---------------- GEMM: g_xw[n,j] = (sum_f A[n,f] W[f,j]) * dinv[n] --------
// Block: 64 nodes x 128 cols, 256 threads, 4 nodes x 8 cols per thread.
__global__ void k_gemm(int src_sel, const float* __restrict__ W) {
    const float* __restrict__ A = src_sel ? g_f1 : g_xT;
    __shared__ float As[64][17];
    __shared__ float Ws[16][132];
    int t = threadIdx.x;
    int tx = t & 15;                   // column group (8 cols)
    int ty = t >> 4;                   // node group (4 nodes)
    int nbase = blockIdx.x * 64;

    float acc[4][8];
#pragma unroll
    for (int i = 0; i < 4; i++)
#pragma unroll
        for (int j = 0; j < 8; j++) acc[i][j] = 0.0f;

    for (int fc = 0; fc < D; fc += 16) {
#pragma unroll
        for (int k = 0; k < 4; k++) {
            int idx = t + k * 256;
            int r = idx >> 4, c = idx & 15;
            int n = nbase + r;
            As[r][c] = (n < N_NODES) ? A[(size_t)n * D + fc + c] : 0.0f;
        }
#pragma unroll
        for (int k = 0; k < 8; k++) {
            int idx = t + k * 256;
            int r = idx >> 7, c = idx & 127;
            Ws[r][c] = W[(fc + r) * D + c];
        }
        __syncthreads();
#pragma unroll
        for (int ff = 0; ff < 16; ff++) {
            const float4* wrow = (const float4*)&Ws[ff][0];
            float4 wa = wrow[tx * 2];
            float4 wb = wrow[tx * 2 + 1];
            float w[8] = {wa.x, wa.y, wa.z, wa.w, wb.x, wb.y, wb.z, wb.w};
#pragma unroll
            for (int i = 0; i < 4; i++) {
                float a = As[ty * 4 + i][ff];
#pragma unroll
                for (int j = 0; j < 8; j++)
                    acc[i][j] += a * w[j];
            }
        }
        __syncthreads();
    }

#pragma unroll
    for (int i = 0; i < 4; i++) {
        int node = nbase + ty * 4 + i;
        if (node >= N_NODES) continue;
        float di = g_deg[node];
        size_t off = (size_t)node * D + tx * 8;
        ((float4*)(g_xw + off))[0] =
            make_float4(acc[i][0]*di, acc[i][1]*di, acc[i][2]*di, acc[i][3]*di);
        ((float4*)(g_xw + off))[1] =
            make_float4(acc[i][4]*di, acc[i][5]*di, acc[i][6]*di, acc[i][7]*di);
    }
}

// ---------------- fused CSR gather + MessageNorm + GELU (+stats) -----------
// msg[d] = dinv[d] * (xw[d] + sum_in xw[src]) + bias; warp per node.
__global__ void k_agg(int stage, const float* __restrict__ bias,
                      const float* __restrict__ scale) {
    __shared__ float s_cs[D], s_cs2[D];
    if (stage) {
        if (threadIdx.x < D) { s_cs[threadIdx.x] = 0.0f; s_cs2[threadIdx.x] = 0.0f; }
        __syncthreads();
    }

    int gw = (blockIdx.x * blockDim.x + threadIdx.x) >> 5;
    int lane = threadIdx.x & 31;
    bool active = gw < N_NODES;
    float4 r = make_float4(0.f, 0.f, 0.f, 0.f);

    if (active) {
        const float4* xw4 = (const float4*)g_xw;
        float4 acc = xw4[(size_t)gw * 32 + lane];       // self-loop term
        int rs  = g_rowstart[gw];
        int end = rs + g_hist[gw];
        int e = rs;
        for (; e + 4 <= end; e += 4) {
            int s0 = g_csrc[e],     s1 = g_csrc[e + 1];
            int s2 = g_csrc[e + 2], s3 = g_csrc[e + 3];
            float4 v0 = xw4[(size_t)s0 * 32 + lane];
            float4 v1 = xw4[(size_t)s1 * 32 + lane];
            float4 v2 = xw4[(size_t)s2 * 32 + lane];
            float4 v3 = xw4[(size_t)s3 * 32 + lane];
            acc.x += (v0.x + v1.x) + (v2.x + v3.x);
            acc.y += (v0.y + v1.y) + (v2.y + v3.y);
            acc.z += (v0.z + v1.z) + (v2.z + v3.z);
            acc.w += (v0.w + v1.w) + (v2.w + v3.w);
        }
        for (; e < end; e++) {
            float4 v = xw4[(size_t)g_csrc[e] * 32 + lane];
            acc.x += v.x; acc.y += v.y; acc.z += v.z; acc.w += v.w;
        }

        float nd = g_deg[gw];
        float4 bb = ((const float4*)bias)[lane];
        float4 m = make_float4(acc.x * nd + bb.x, acc.y * nd + bb.y,
                               acc.z * nd + bb.z, acc.w * nd + bb.w);

        size_t off = (size_t)gw * D;
        const float* xprev = stage ? g_f1 : g_xT;
        float4 xv = ((const float4*)(xprev + off))[lane];

        float ms = m.x*m.x + m.y*m.y + m.z*m.z + m.w*m.w;
        float xs = xv.x*xv.x + xv.y*xv.y + xv.z*xv.z + xv.w*xv.w;
#pragma unroll
        for (int o = 16; o; o >>= 1) {
            ms += __shfl_xor_sync(0xFFFFFFFFu, ms, o);
            xs += __shfl_xor_sync(0xFFFFFFFFu, xs, o);
        }
        float coef = scale[0] * sqrtf(xs) / fmaxf(sqrtf(ms), 1e-12f);

        r.x = gelu_exact(xv.x + coef * m.x);
        r.y = gelu_exact(xv.y + coef * m.y);
        r.z = gelu_exact(xv.z + coef * m.z);
        r.w = gelu_exact(xv.w + coef * m.w);

        if (stage) {
            float4 rv = ((const float4*)(g_xT + off))[lane];
            r.x += rv.x; r.y += rv.y; r.z += rv.z; r.w += rv.w;
        }
        float* out = stage ? g_y : g_f1;
        ((float4*)(out + off))[lane] = r;
    }

    if (stage) {
        if (active) {
            int c0 = lane * 4;
            atomicAdd(&s_cs [c0    ], r.x); atomicAdd(&s_cs2[c0    ], r.x * r.x);
            atomicAdd(&s_cs [c0 + 1], r.y); atomicAdd(&s_cs2[c0 + 1], r.y * r.y);
            atomicAdd(&s_cs [c0 + 2], r.z); atomicAdd(&s_cs2[c0 + 2], r.z * r.z);
            atomicAdd(&s_cs [c0 + 3], r.w); atomicAdd(&s_cs2[c0 + 3], r.w * r.w);
        }
        __syncthreads();
        if (threadIdx.x < D) {
            atomicAdd(&g_cs [threadIdx.x], s_cs [threadIdx.x]);
            atomicAdd(&g_cs2[threadIdx.x], s_cs2[threadIdx.x]);
        }
    }
}

// ---------------- finalize: GraphNorm + GELU -------------------------------
__global__ void k_final(const float* __restrict__ gnw,
                        const float* __restrict__ gnb,
                        const float* __restrict__ gnm,
                        float* __restrict__ out) {
    const float invN = 1.0f / (float)N_NODES;
    for (int idx = blockIdx.x * blockDim.x + threadIdx.x;
         idx < N_NODES * D; idx += gridDim.x * blockDim.x) {
        int c = idx & (D - 1);
        float mean = g_cs[c]  * invN;
        float ey2  = g_cs2[c] * invN;
        float msc  = gnm[c];
        float sub  = g_y[idx] - mean * msc;
        float var  = ey2 - 2.0f * msc * mean * mean + msc * msc * mean * mean;
        float o = gnw[c] * sub * rsqrtf(var + 1e-5f) + gnb[c];
        out[idx] = gelu_exact(o);
    }
}

// ---------------- launch ----------------------------------------------------
extern "C" void kernel_launch(void* const* d_in, const int* in_sizes, int n_in,
                              void* d_out, int out_size) {
    const float* X   = (const float*)d_in[0];
    const int*   ei  = (const int*)  d_in[1];     // int32 (JAX x64 disabled)
    const float* W1  = (const float*)d_in[2];
    const float* b1  = (const float*)d_in[3];
    const float* s1  = (const float*)d_in[4];
    const float* W2  = (const float*)d_in[5];
    const float* b2  = (const float*)d_in[6];
    const float* s2  = (const float*)d_in[7];
    const float* gnw = (const float*)d_in[8];
    const float* gnb = (const float*)d_in[9];
    const float* gnm = (const float*)d_in[10];
    float* out = (float*)d_out;

    const int TB = 256;
    k_init  <<<(N_NODES + TB - 1) / TB, TB>>>();
    k_deg   <<<(N_EDGES + TB - 1) / TB, TB>>>(ei);
    k_rsqrt <<<(N_NODES + TB - 1) / TB, TB>>>();

    // CSR build (reused by both layers)
    k_scan1 <<<N_SBLK, SCAN_B>>>();
    k_scan2 <<<1, 64>>>();
    k_scan3 <<<(N_NODES + TB - 1) / TB, TB>>>();
    k_fill  <<<(N_EDGES + TB - 1) / TB, TB>>>(ei);

    dim3 tg((N_NODES + 31) / 32, D / 32);
    k_transpose<<<tg, dim3(32, 8)>>>(X);

    int gemm_blocks = (N_NODES + 63) / 64;
    int agg_blocks  = (N_NODES * 32 + TB - 1) / TB;

    // ---- layer 1 ----
    k_gemm <<<gemm_blocks, TB>>>(0, W1);
    k_agg  <<<agg_blocks, TB>>>(0, b1, s1);

    // ---- layer 2 ----
    k_gemm <<<gemm_blocks, TB>>>(1, W2);
    k_agg  <<<agg_blocks, TB>>>(1, b2, s2);

    // ---- GraphNorm + GELU ----
    k_final<<<4096, TB>>>(gnw, gnb, gnm, out);
}

// round 5
// speedup vs baseline: 2.3929x; 1.0873x over previous
#include <cuda_runtime.h>
#include <math.h>

#define N_NODES 50000
#define N_EDGES 800000
#define D 128
#define SCAN_B 1024
#define N_SBLK ((N_NODES + SCAN_B - 1) / SCAN_B)   // 49

// ---------------- scratch (device globals; re-initialized every launch) ----
__device__ float g_xT [(size_t)N_NODES * D];   // X transposed: [N,128]
__device__ float g_xw [(size_t)N_NODES * D];   // GEMM out, pre-scaled by dinv[n]
__device__ float g_f1 [(size_t)N_NODES * D];   // layer-1 output
__device__ float g_y  [(size_t)N_NODES * D];   // layer-2 output (+residual)
__device__ float g_deg[N_NODES];               // dinv = rsqrt(1 + in_deg)
__device__ int   g_hist[N_NODES];              // in-degree (no self loop)
__device__ int   g_rowstart[N_NODES];          // CSR row starts (by dst)
__device__ int   g_cursor[N_NODES];            // fill cursors
__device__ int   g_csrc[N_EDGES];              // CSR src indices
__device__ int   g_bsum[64];                   // scan block sums
__device__ float g_cs [D];                     // column sum of y
__device__ float g_cs2[D];                     // column sum of y^2

__device__ __forceinline__ float gelu_exact(float v) {
    return v * normcdff(v);     // jax.nn.gelu(approximate=False)
}

__device__ __forceinline__ void fma2(unsigned long long& acc,
                                     unsigned long long a,
                                     unsigned long long b) {
    asm("fma.rn.f32x2 %0, %1, %2, %0;" : "+l"(acc) : "l"(a), "l"(b));
}

// ---------------- init ------------------------------------------------------
__global__ void k_init() {
    int i = blockIdx.x * blockDim.x + threadIdx.x;
    if (i < N_NODES) g_hist[i] = 0;
    if (i < D) { g_cs[i] = 0.0f; g_cs2[i] = 0.0f; }
}

// ---------------- in-degree histogram (edge_index is INT32) ----------------
__global__ void k_deg(const int* __restrict__ ei) {
    int e = blockIdx.x * blockDim.x + threadIdx.x;
    if (e < N_EDGES) atomicAdd(&g_hist[ei[N_EDGES + e]], 1);
}

__global__ void k_rsqrt() {
    int i = blockIdx.x * blockDim.x + threadIdx.x;
    if (i < N_NODES) g_deg[i] = rsqrtf((float)g_hist[i] + 1.0f);
}

// ---------------- prefix scan of g_hist -> g_rowstart (exclusive) ----------
__global__ void k_scan1() {
    __shared__ int sh[SCAN_B];
    int t = threadIdx.x;
    int i = blockIdx.x * SCAN_B + t;
    int v = (i < N_NODES) ? g_hist[i] : 0;
    sh[t] = v;
    __syncthreads();
    for (int off = 1; off < SCAN_B; off <<= 1) {
        int x = (t >= off) ? sh[t - off] : 0;
        __syncthreads();
        sh[t] += x;
        __syncthreads();
    }
    if (i < N_NODES) g_rowstart[i] = sh[t] - v;
    if (t == SCAN_B - 1) g_bsum[blockIdx.x] = sh[t];
}

__global__ void k_scan2() {     // single block, 64 threads
    __shared__ int sh[64];
    int t = threadIdx.x;
    int v = (t < N_SBLK) ? g_bsum[t] : 0;
    sh[t] = v;
    __syncthreads();
    for (int off = 1; off < 64; off <<= 1) {
        int x = (t >= off) ? sh[t - off] : 0;
        __syncthreads();
        sh[t] += x;
        __syncthreads();
    }
    g_bsum[t] = sh[t] - v;
}

__global__ void k_scan3() {
    int i = blockIdx.x * blockDim.x + threadIdx.x;
    if (i < N_NODES) {
        int rs = g_rowstart[i] + g_bsum[i / SCAN_B];
        g_rowstart[i] = rs;
        g_cursor[i]   = rs;
    }
}

// ---------------- CSR fill ---------------------------------------------------
__global__ void k_fill(const int* __restrict__ ei) {
    int e = blockIdx.x * blockDim.x + threadIdx.x;
    if (e < N_EDGES) {
        int s = ei[e];
        int d = ei[N_EDGES + e];
        int pos = atomicAdd(&g_cursor[d], 1);
        g_csrc[pos] = s;
    }
}

// ---------------- transpose X [128,N] -> xT [N,128] ------------------------
__global__ void k_transpose(const float* __restrict__ X) {
    __shared__ float s[32][33];
    int n0 = blockIdx.x * 32;
    int f0 = blockIdx.y * 32;
    int tx = threadIdx.x, ty = threadIdx.y;          // (32, 8)
    int n = n0 + tx;
#pragma unroll
    for (int i = 0; i < 4; i++) {
        int f = f0 + ty + i * 8;
        if (n < N_NODES) s[ty + i * 8][tx] = X[(size_t)f * N_NODES + n];
    }
    __syncthreads();
#pragma unroll
    for (int i = 0; i < 4; i++) {
        int n2 = n0 + ty + i * 8;
        int f2 = f0 + tx;
        if (n2 < N_NODES) g_xT[(size_t)n2 * D + f2] = s[tx][ty + i * 8];
    }
}

// ---------------- GEMM (f32x2): g_xw[n,j] = (sum_f A[n,f] W[f,j])*dinv[n] --
// Block: 128 nodes x 128 cols, 256 threads, 8 nodes x 8 cols per thread.
// A staged as duplicated float2 pairs so packed (a,a) comes from one LDS.64.
__global__ void __launch_bounds__(256) k_gemm(int src_sel,
                                              const float* __restrict__ W) {
    const float* __restrict__ A = src_sel ? g_f1 : g_xT;
    __shared__ float2 As2[128][16];    // 16 KB: (a,a) pairs, 16-col k-chunk
    __shared__ float  Ws[16][132];     // 8.25 KB padded
    int t  = threadIdx.x;
    int tx = t & 15;                   // column group (8 cols)
    int ty = t >> 4;                   // node group (8 nodes)
    int nbase = blockIdx.x * 128;

    unsigned long long acc[8][4];
#pragma unroll
    for (int i = 0; i < 8; i++)
#pragma unroll
        for (int p = 0; p < 4; p++) acc[i][p] = 0ull;

    for (int fc = 0; fc < D; fc += 16) {
#pragma unroll
        for (int k = 0; k < 8; k++) {           // 128x16 A chunk (dup pairs)
            int idx = t + k * 256;
            int r = idx >> 4, c = idx & 15;
            int n = nbase + r;
            float v = (n < N_NODES) ? A[(size_t)n * D + fc + c] : 0.0f;
            As2[r][c] = make_float2(v, v);
        }
#pragma unroll
        for (int k = 0; k < 8; k++) {           // 16x128 W chunk
            int idx = t + k * 256;
            int r = idx >> 7, c = idx & 127;
            Ws[r][c] = W[(fc + r) * D + c];
        }
        __syncthreads();
#pragma unroll
        for (int ff = 0; ff < 16; ff++) {
            const unsigned long long* wrow =
                (const unsigned long long*)&Ws[ff][tx * 8];
            unsigned long long w0 = wrow[0];
            unsigned long long w1 = wrow[1];
            unsigned long long w2 = wrow[2];
            unsigned long long w3 = wrow[3];
#pragma unroll
            for (int i = 0; i < 8; i++) {
                unsigned long long a2 =
                    *(const unsigned long long*)&As2[ty * 8 + i][ff];
                fma2(acc[i][0], a2, w0);
                fma2(acc[i][1], a2, w1);
                fma2(acc[i][2], a2, w2);
                fma2(acc[i][3], a2, w3);
            }
        }
        __syncthreads();
    }

#pragma unroll
    for (int i = 0; i < 8; i++) {
        int node = nbase + ty * 8 + i;
        if (node >= N_NODES) continue;
        float di = g_deg[node];
        size_t off = (size_t)node * D + tx * 8;
        float2 p0 = *(float2*)&acc[i][0];
        float2 p1 = *(float2*)&acc[i][1];
        float2 p2 = *(float2*)&acc[i][2];
        float2 p3 = *(float2*)&acc[i][3];
        ((float4*)(g_xw + off))[0] =
            make_float4(p0.x * di, p0.y * di, p1.x * di, p1.y * di);
        ((float4*)(g_xw + off))[1] =
            make_float4(p2.x * di, p2.y * di, p3.x * di, p3.y * di);
    }
}

// ---------------- fused CSR gather + MessageNorm + GELU (+stats) -----------
// msg[d] = dinv[d] * (xw[d] + sum_in xw[src]) + bias; warp per node.
__global__ void k_agg(int stage, const float* __restrict__ bias,
                      const float* __restrict__ scale) {
    __shared__ float s_cs[D], s_cs2[D];
    if (stage) {
        if (threadIdx.x < D) { s_cs[threadIdx.x] = 0.0f; s_cs2[threadIdx.x] = 0.0f; }
        __syncthreads();
    }

    int gw = (blockIdx.x * blockDim.x + threadIdx.x) >> 5;
    int lane = threadIdx.x & 31;
    bool active = gw < N_NODES;
    float4 r = make_float4(0.f, 0.f, 0.f, 0.f);

    if (active) {
        const float4* xw4 = (const float4*)g_xw;
        float4 acc = xw4[(size_t)gw * 32 + lane];       // self-loop term
        int rs  = g_rowstart[gw];
        int end = rs + g_hist[gw];
        int e = rs;
        for (; e + 4 <= end; e += 4) {
            int s0 = g_csrc[e],     s1 = g_csrc[e + 1];
            int s2 = g_csrc[e + 2], s3 = g_csrc[e + 3];
            float4 v0 = xw4[(size_t)s0 * 32 + lane];
            float4 v1 = xw4[(size_t)s1 * 32 + lane];
            float4 v2 = xw4[(size_t)s2 * 32 + lane];
            float4 v3 = xw4[(size_t)s3 * 32 + lane];
            acc.x += (v0.x + v1.x) + (v2.x + v3.x);
            acc.y += (v0.y + v1.y) + (v2.y + v3.y);
            acc.z += (v0.z + v1.z) + (v2.z + v3.z);
            acc.w += (v0.w + v1.w) + (v2.w + v3.w);
        }
        for (; e < end; e++) {
            float4 v = xw4[(size_t)g_csrc[e] * 32 + lane];
            acc.x += v.x; acc.y += v.y; acc.z += v.z; acc.w += v.w;
        }

        float nd = g_deg[gw];
        float4 bb = ((const float4*)bias)[lane];
        float4 m = make_float4(acc.x * nd + bb.x, acc.y * nd + bb.y,
                               acc.z * nd + bb.z, acc.w * nd + bb.w);

        size_t off = (size_t)gw * D;
        const float* xprev = stage ? g_f1 : g_xT;
        float4 xv = ((const float4*)(xprev + off))[lane];

        float ms = m.x*m.x + m.y*m.y + m.z*m.z + m.w*m.w;
        float xs = xv.x*xv.x + xv.y*xv.y + xv.z*xv.z + xv.w*xv.w;
#pragma unroll
        for (int o = 16; o; o >>= 1) {
            ms += __shfl_xor_sync(0xFFFFFFFFu, ms, o);
            xs += __shfl_xor_sync(0xFFFFFFFFu, xs, o);
        }
        float coef = scale[0] * sqrtf(xs) / fmaxf(sqrtf(ms), 1e-12f);

        r.x = gelu_exact(xv.x + coef * m.x);
        r.y = gelu_exact(xv.y + coef * m.y);
        r.z = gelu_exact(xv.z + coef * m.z);
        r.w = gelu_exact(xv.w + coef * m.w);

        if (stage) {
            float4 rv = ((const float4*)(g_xT + off))[lane];
            r.x += rv.x; r.y += rv.y; r.z += rv.z; r.w += rv.w;
        }
        float* out = stage ? g_y : g_f1;
        ((float4*)(out + off))[lane] = r;
    }

    if (stage) {
        if (active) {
            int c0 = lane * 4;
            atomicAdd(&s_cs [c0    ], r.x); atomicAdd(&s_cs2[c0    ], r.x * r.x);
            atomicAdd(&s_cs [c0 + 1], r.y); atomicAdd(&s_cs2[c0 + 1], r.y * r.y);
            atomicAdd(&s_cs [c0 + 2], r.z); atomicAdd(&s_cs2[c0 + 2], r.z * r.z);
            atomicAdd(&s_cs [c0 + 3], r.w); atomicAdd(&s_cs2[c0 + 3], r.w * r.w);
        }
        __syncthreads();
        if (threadIdx.x < D) {
            atomicAdd(&g_cs [threadIdx.x], s_cs [threadIdx.x]);
            atomicAdd(&g_cs2[threadIdx.x], s_cs2[threadIdx.x]);
        }
    }
}

// ---------------- finalize: GraphNorm + GELU -------------------------------
__global__ void k_final(const float* __restrict__ gnw,
                        const float* __restrict__ gnb,
                        const float* __restrict__ gnm,
                        float* __restrict__ out) {
    const float invN = 1.0f / (float)N_NODES;
    for (int idx = blockIdx.x * blockDim.x + threadIdx.x;
         idx < N_NODES * D; idx += gridDim.x * blockDim.x) {
        int c = idx & (D - 1);
        float mean = g_cs[c]  * invN;
        float ey2  = g_cs2[c] * invN;
        float msc  = gnm[c];
        float sub  = g_y[idx] - mean * msc;
        float var  = ey2 - 2.0f * msc * mean * mean + msc * msc * mean * mean;
        float o = gnw[c] * sub * rsqrtf(var + 1e-5f) + gnb[c];
        out[idx] = gelu_exact(o);
    }
}

// ---------------- launch ----------------------------------------------------
extern "C" void kernel_launch(void* const* d_in, const int* in_sizes, int n_in,
                              void* d_out, int out_size) {
    const float* X   = (const float*)d_in[0];
    const int*   ei  = (const int*)  d_in[1];     // int32 (JAX x64 disabled)
    const float* W1  = (const float*)d_in[2];
    const float* b1  = (const float*)d_in[3];
    const float* s1  = (const float*)d_in[4];
    const float* W2  = (const float*)d_in[5];
    const float* b2  = (const float*)d_in[6];
    const float* s2  = (const float*)d_in[7];
    const float* gnw = (const float*)d_in[8];
    const float* gnb = (const float*)d_in[9];
    const float* gnm = (const float*)d_in[10];
    float* out = (float*)d_out;

    const int TB = 256;
    k_init  <<<(N_NODES + TB - 1) / TB, TB>>>();
    k_deg   <<<(N_EDGES + TB - 1) / TB, TB>>>(ei);
    k_rsqrt <<<(N_NODES + TB - 1) / TB, TB>>>();

    // CSR build (reused by both layers)
    k_scan1 <<<N_SBLK, SCAN_B>>>();
    k_scan2 <<<1, 64>>>();
    k_scan3 <<<(N_NODES + TB - 1) / TB, TB>>>();
    k_fill  <<<(N_EDGES + TB - 1) / TB, TB>>>(ei);

    dim3 tg((N_NODES + 31) / 32, D / 32);
    k_transpose<<<tg, dim3(32, 8)>>>(X);

    int gemm_blocks = (N_NODES + 127) / 128;
    int agg_blocks  = (N_NODES * 32 + TB - 1) / TB;

    // ---- layer 1 ----
    k_gemm <<<gemm_blocks, TB>>>(0, W1);
    k_agg  <<<agg_blocks, TB>>>(0, b1, s1);

    // ---- layer 2 ----
    k_gemm <<<gemm_blocks, TB>>>(1, W2);
    k_agg  <<<agg_blocks, TB>>>(1, b2, s2);

    // ---- GraphNorm + GELU ----
    k_final<<<4096, TB>>>(gnw, gnb, gnm, out);
}

// round 6
// speedup vs baseline: 2.5108x; 1.0493x over previous
#include <cuda_runtime.h>
#include <math.h>

#define N_NODES 50000
#define N_EDGES 800000
#define D 128
#define SCAN_B 1024
#define N_SBLK ((N_NODES + SCAN_B - 1) / SCAN_B)   // 49

// ---------------- scratch (device globals; self-restoring across replays) --
__device__ float g_xT [(size_t)N_NODES * D];   // X transposed: [N,128]
__device__ float g_xw [(size_t)N_NODES * D];   // GEMM out, pre-scaled by dinv[n]
__device__ float g_f1 [(size_t)N_NODES * D];   // layer-1 output
__device__ float g_y  [(size_t)N_NODES * D];   // layer-2 output (+residual)
__device__ float g_deg[N_NODES];               // dinv = rsqrt(1 + in_deg)
__device__ int   g_hist[N_NODES];              // in-degree (zeroed by k_final)
__device__ int   g_rowstart[N_NODES];          // CSR row starts (by dst)
__device__ int   g_cursor[N_NODES];            // fill cursors
__device__ int   g_csrc[N_EDGES];              // CSR src indices
__device__ int   g_bsum[64];                   // scan block sums
__device__ float g_cs [D];                     // col sum of y  (zeroed by gemm L1)
__device__ float g_cs2[D];                     // col sum of y^2

__device__ __forceinline__ float gelu_exact(float v) {
    return v * normcdff(v);     // jax.nn.gelu(approximate=False)
}

__device__ __forceinline__ void fma2(unsigned long long& acc,
                                     unsigned long long a,
                                     unsigned long long b) {
    asm("fma.rn.f32x2 %0, %1, %2, %0;" : "+l"(acc) : "l"(a), "l"(b));
}

// ---------------- in-degree histogram (edge_index is INT32) ----------------
__global__ void k_deg(const int* __restrict__ ei) {
    int e = blockIdx.x * blockDim.x + threadIdx.x;
    if (e < N_EDGES) atomicAdd(&g_hist[ei[N_EDGES + e]], 1);
}

// ---------------- scan pass 1 (+ fused dinv = rsqrt(deg+1)) ----------------
__global__ void k_scan1() {
    __shared__ int sh[SCAN_B];
    int t = threadIdx.x;
    int i = blockIdx.x * SCAN_B + t;
    int v = (i < N_NODES) ? g_hist[i] : 0;
    if (i < N_NODES) g_deg[i] = rsqrtf((float)v + 1.0f);
    sh[t] = v;
    __syncthreads();
    for (int off = 1; off < SCAN_B; off <<= 1) {
        int x = (t >= off) ? sh[t - off] : 0;
        __syncthreads();
        sh[t] += x;
        __syncthreads();
    }
    if (i < N_NODES) g_rowstart[i] = sh[t] - v;
    if (t == SCAN_B - 1) g_bsum[blockIdx.x] = sh[t];
}

__global__ void k_scan2() {     // single block, 64 threads
    __shared__ int sh[64];
    int t = threadIdx.x;
    int v = (t < N_SBLK) ? g_bsum[t] : 0;
    sh[t] = v;
    __syncthreads();
    for (int off = 1; off < 64; off <<= 1) {
        int x = (t >= off) ? sh[t - off] : 0;
        __syncthreads();
        sh[t] += x;
        __syncthreads();
    }
    g_bsum[t] = sh[t] - v;
}

__global__ void k_scan3() {
    int i = blockIdx.x * blockDim.x + threadIdx.x;
    if (i < N_NODES) {
        int rs = g_rowstart[i] + g_bsum[i / SCAN_B];
        g_rowstart[i] = rs;
        g_cursor[i]   = rs;
    }
}

// ---------------- CSR fill ---------------------------------------------------
__global__ void k_fill(const int* __restrict__ ei) {
    int e = blockIdx.x * blockDim.x + threadIdx.x;
    if (e < N_EDGES) {
        int s = ei[e];
        int d = ei[N_EDGES + e];
        int pos = atomicAdd(&g_cursor[d], 1);
        g_csrc[pos] = s;
    }
}

// ---------------- transpose X [128,N] -> xT [N,128] ------------------------
__global__ void k_transpose(const float* __restrict__ X) {
    __shared__ float s[32][33];
    int n0 = blockIdx.x * 32;
    int f0 = blockIdx.y * 32;
    int tx = threadIdx.x, ty = threadIdx.y;          // (32, 8)
    int n = n0 + tx;
#pragma unroll
    for (int i = 0; i < 4; i++) {
        int f = f0 + ty + i * 8;
        if (n < N_NODES) s[ty + i * 8][tx] = X[(size_t)f * N_NODES + n];
    }
    __syncthreads();
#pragma unroll
    for (int i = 0; i < 4; i++) {
        int n2 = n0 + ty + i * 8;
        int f2 = f0 + tx;
        if (n2 < N_NODES) g_xT[(size_t)n2 * D + f2] = s[tx][ty + i * 8];
    }
}

// ---------------- GEMM (f32x2): g_xw[n,j] = (sum_f A[n,f] W[f,j])*dinv[n] --
// Block: 128 nodes x 128 cols, 256 threads, 8 nodes x 8 cols per thread.
// Layer-1 block 0 also zeroes the GraphNorm stat accumulators (runs before
// agg stage 1 writes them; keeps state self-restoring across graph replays).
__global__ void __launch_bounds__(256) k_gemm(int src_sel,
                                              const float* __restrict__ W) {
    const float* __restrict__ A = src_sel ? g_f1 : g_xT;
    if (src_sel == 0 && blockIdx.x == 0 && threadIdx.x < D) {
        g_cs[threadIdx.x] = 0.0f;
        g_cs2[threadIdx.x] = 0.0f;
    }
    __shared__ float2 As2[128][16];    // 16 KB: (a,a) pairs, 16-col k-chunk
    __shared__ float  Ws[16][132];     // 8.25 KB padded
    int t  = threadIdx.x;
    int tx = t & 15;                   // column group (8 cols)
    int ty = t >> 4;                   // node group (8 nodes)
    int nbase = blockIdx.x * 128;

    unsigned long long acc[8][4];
#pragma unroll
    for (int i = 0; i < 8; i++)
#pragma unroll
        for (int p = 0; p < 4; p++) acc[i][p] = 0ull;

    for (int fc = 0; fc < D; fc += 16) {
#pragma unroll
        for (int k = 0; k < 8; k++) {           // 128x16 A chunk (dup pairs)
            int idx = t + k * 256;
            int r = idx >> 4, c = idx & 15;
            int n = nbase + r;
            float v = (n < N_NODES) ? A[(size_t)n * D + fc + c] : 0.0f;
            As2[r][c] = make_float2(v, v);
        }
#pragma unroll
        for (int k = 0; k < 8; k++) {           // 16x128 W chunk
            int idx = t + k * 256;
            int r = idx >> 7, c = idx & 127;
            Ws[r][c] = W[(fc + r) * D + c];
        }
        __syncthreads();
#pragma unroll
        for (int ff = 0; ff < 16; ff++) {
            const unsigned long long* wrow =
                (const unsigned long long*)&Ws[ff][tx * 8];
            unsigned long long w0 = wrow[0];
            unsigned long long w1 = wrow[1];
            unsigned long long w2 = wrow[2];
            unsigned long long w3 = wrow[3];
#pragma unroll
            for (int i = 0; i < 8; i++) {
                unsigned long long a2 =
                    *(const unsigned long long*)&As2[ty * 8 + i][ff];
                fma2(acc[i][0], a2, w0);
                fma2(acc[i][1], a2, w1);
                fma2(acc[i][2], a2, w2);
                fma2(acc[i][3], a2, w3);
            }
        }
        __syncthreads();
    }

#pragma unroll
    for (int i = 0; i < 8; i++) {
        int node = nbase + ty * 8 + i;
        if (node >= N_NODES) continue;
        float di = g_deg[node];
        size_t off = (size_t)node * D + tx * 8;
        float2 p0 = *(float2*)&acc[i][0];
        float2 p1 = *(float2*)&acc[i][1];
        float2 p2 = *(float2*)&acc[i][2];
        float2 p3 = *(float2*)&acc[i][3];
        ((float4*)(g_xw + off))[0] =
            make_float4(p0.x * di, p0.y * di, p1.x * di, p1.y * di);
        ((float4*)(g_xw + off))[1] =
            make_float4(p2.x * di, p2.y * di, p3.x * di, p3.y * di);
    }
}

// ---------------- fused CSR gather + MessageNorm + GELU (+stats) -----------
// msg[d] = dinv[d] * (xw[d] + sum_in xw[src]) + bias; warp per node.
__global__ void __launch_bounds__(512) k_agg(int stage,
                                             const float* __restrict__ bias,
                                             const float* __restrict__ scale) {
    __shared__ float s_cs[D], s_cs2[D];
    if (stage) {
        if (threadIdx.x < D) { s_cs[threadIdx.x] = 0.0f; s_cs2[threadIdx.x] = 0.0f; }
        __syncthreads();
    }

    int gw = (blockIdx.x * blockDim.x + threadIdx.x) >> 5;
    int lane = threadIdx.x & 31;
    bool active = gw < N_NODES;
    float4 r = make_float4(0.f, 0.f, 0.f, 0.f);

    if (active) {
        const float4* xw4 = (const float4*)g_xw;
        float4 acc = xw4[(size_t)gw * 32 + lane];       // self-loop term
        int rs  = g_rowstart[gw];
        int end = rs + g_hist[gw];
        int e = rs;
        for (; e + 8 <= end; e += 8) {
            int s0 = g_csrc[e],     s1 = g_csrc[e + 1];
            int s2 = g_csrc[e + 2], s3 = g_csrc[e + 3];
            int s4 = g_csrc[e + 4], s5 = g_csrc[e + 5];
            int s6 = g_csrc[e + 6], s7 = g_csrc[e + 7];
            float4 v0 = xw4[(size_t)s0 * 32 + lane];
            float4 v1 = xw4[(size_t)s1 * 32 + lane];
            float4 v2 = xw4[(size_t)s2 * 32 + lane];
            float4 v3 = xw4[(size_t)s3 * 32 + lane];
            float4 v4 = xw4[(size_t)s4 * 32 + lane];
            float4 v5 = xw4[(size_t)s5 * 32 + lane];
            float4 v6 = xw4[(size_t)s6 * 32 + lane];
            float4 v7 = xw4[(size_t)s7 * 32 + lane];
            acc.x += ((v0.x + v1.x) + (v2.x + v3.x)) + ((v4.x + v5.x) + (v6.x + v7.x));
            acc.y += ((v0.y + v1.y) + (v2.y + v3.y)) + ((v4.y + v5.y) + (v6.y + v7.y));
            acc.z += ((v0.z + v1.z) + (v2.z + v3.z)) + ((v4.z + v5.z) + (v6.z + v7.z));
            acc.w += ((v0.w + v1.w) + (v2.w + v3.w)) + ((v4.w + v5.w) + (v6.w + v7.w));
        }
        for (; e < end; e++) {
            float4 v = xw4[(size_t)g_csrc[e] * 32 + lane];
            acc.x += v.x; acc.y += v.y; acc.z += v.z; acc.w += v.w;
        }

        float nd = g_deg[gw];
        float4 bb = ((const float4*)bias)[lane];
        float4 m = make_float4(acc.x * nd + bb.x, acc.y * nd + bb.y,
                               acc.z * nd + bb.z, acc.w * nd + bb.w);

        size_t off = (size_t)gw * D;
        const float* xprev = stage ? g_f1 : g_xT;
        float4 xv = ((const float4*)(xprev + off))[lane];

        float ms = m.x*m.x + m.y*m.y + m.z*m.z + m.w*m.w;
        float xs = xv.x*xv.x + xv.y*xv.y + xv.z*xv.z + xv.w*xv.w;
#pragma unroll
        for (int o = 16; o; o >>= 1) {
            ms += __shfl_xor_sync(0xFFFFFFFFu, ms, o);
            xs += __shfl_xor_sync(0xFFFFFFFFu, xs, o);
        }
        float coef = scale[0] * sqrtf(xs) / fmaxf(sqrtf(ms), 1e-12f);

        r.x = gelu_exact(xv.x + coef * m.x);
        r.y = gelu_exact(xv.y + coef * m.y);
        r.z = gelu_exact(xv.z + coef * m.z);
        r.w = gelu_exact(xv.w + coef * m.w);

        if (stage) {
            float4 rv = ((const float4*)(g_xT + off))[lane];
            r.x += rv.x; r.y += rv.y; r.z += rv.z; r.w += rv.w;
        }
        float* out = stage ? g_y : g_f1;
        ((float4*)(out + off))[lane] = r;
    }

    if (stage) {
        if (active) {
            int c0 = lane * 4;
            atomicAdd(&s_cs [c0    ], r.x); atomicAdd(&s_cs2[c0    ], r.x * r.x);
            atomicAdd(&s_cs [c0 + 1], r.y); atomicAdd(&s_cs2[c0 + 1], r.y * r.y);
            atomicAdd(&s_cs [c0 + 2], r.z); atomicAdd(&s_cs2[c0 + 2], r.z * r.z);
            atomicAdd(&s_cs [c0 + 3], r.w); atomicAdd(&s_cs2[c0 + 3], r.w * r.w);
        }
        __syncthreads();
        if (threadIdx.x < D) {
            atomicAdd(&g_cs [threadIdx.x], s_cs [threadIdx.x]);
            atomicAdd(&g_cs2[threadIdx.x], s_cs2[threadIdx.x]);
        }
    }
}

// ---------------- finalize: GraphNorm + GELU (+ restore g_hist = 0) --------
__global__ void k_final(const float* __restrict__ gnw,
                        const float* __restrict__ gnb,
                        const float* __restrict__ gnm,
                        float* __restrict__ out) {
    const float invN = 1.0f / (float)N_NODES;
    for (int idx = blockIdx.x * blockDim.x + threadIdx.x;
         idx < N_NODES * D; idx += gridDim.x * blockDim.x) {
        if (idx < N_NODES) g_hist[idx] = 0;     // self-restore for next replay
        int c = idx & (D - 1);
        float mean = g_cs[c]  * invN;
        float ey2  = g_cs2[c] * invN;
        float msc  = gnm[c];
        float sub  = g_y[idx] - mean * msc;
        float var  = ey2 - 2.0f * msc * mean * mean + msc * msc * mean * mean;
        float o = gnw[c] * sub * rsqrtf(var + 1e-5f) + gnb[c];
        out[idx] = gelu_exact(o);
    }
}

// ---------------- launch ----------------------------------------------------
extern "C" void kernel_launch(void* const* d_in, const int* in_sizes, int n_in,
                              void* d_out, int out_size) {
    const float* X   = (const float*)d_in[0];
    const int*   ei  = (const int*)  d_in[1];     // int32 (JAX x64 disabled)
    const float* W1  = (const float*)d_in[2];
    const float* b1  = (const float*)d_in[3];
    const float* s1  = (const float*)d_in[4];
    const float* W2  = (const float*)d_in[5];
    const float* b2  = (const float*)d_in[6];
    const float* s2  = (const float*)d_in[7];
    const float* gnw = (const float*)d_in[8];
    const float* gnb = (const float*)d_in[9];
    const float* gnm = (const float*)d_in[10];
    float* out = (float*)d_out;

    const int TB = 256;
    // CSR build + norms (g_hist arrives zeroed: module load / previous k_final)
    k_deg   <<<(N_EDGES + TB - 1) / TB, TB>>>(ei);
    k_scan1 <<<N_SBLK, SCAN_B>>>();
    k_scan2 <<<1, 64>>>();
    k_scan3 <<<(N_NODES + TB - 1) / TB, TB>>>();
    k_fill  <<<(N_EDGES + TB - 1) / TB, TB>>>(ei);

    dim3 tg((N_NODES + 31) / 32, D / 32);
    k_transpose<<<tg, dim3(32, 8)>>>(X);

    int gemm_blocks = (N_NODES + 127) / 128;
    int agg_blocks  = (N_NODES * 32 + 511) / 512;

    // ---- layer 1 ----
    k_gemm <<<gemm_blocks, TB>>>(0, W1);
    k_agg  <<<agg_blocks, 512>>>(0, b1, s1);

    // ---- layer 2 ----
    k_gemm <<<gemm_blocks, TB>>>(1, W2);
    k_agg  <<<agg_blocks, 512>>>(1, b2, s2);

    // ---- GraphNorm + GELU ----
    k_final<<<4096, TB>>>(gnw, gnb, gnm, out);
}

// round 7
// speedup vs baseline: 2.6139x; 1.0411x over previous
#include <cuda_runtime.h>
#include <math.h>

#define N_NODES 50000
#define N_EDGES 800000
#define D 128
#define SCAN_B 1024
#define N_SBLK ((N_NODES + SCAN_B - 1) / SCAN_B)   // 49

// ---------------- scratch (device globals; self-restoring across replays) --
__device__ float g_xT [(size_t)N_NODES * D];   // X transposed: [N,128]
__device__ float g_xw [(size_t)N_NODES * D];   // GEMM out (L1 raw, L2 pre-scaled)
__device__ float g_f1 [(size_t)N_NODES * D];   // layer-1 output
__device__ float g_y  [(size_t)N_NODES * D];   // layer-2 output (+residual)
__device__ float g_deg[N_NODES];               // dinv = rsqrt(1 + in_deg)
__device__ int   g_hist[N_NODES];              // in-degree (zeroed by k_final)
__device__ int   g_rowstart[N_NODES];          // CSR row starts (by dst)
__device__ int   g_cursor[N_NODES];            // fill cursors
__device__ int   g_csrc[N_EDGES];              // CSR src indices
__device__ int   g_bsum[64];                   // scan block sums
__device__ float g_cs [D];                     // col sum of y  (zeroed by gemm L1)
__device__ float g_cs2[D];                     // col sum of y^2

__device__ __forceinline__ float gelu_exact(float v) {
    return v * normcdff(v);     // jax.nn.gelu(approximate=False)
}

__device__ __forceinline__ void fma2(unsigned long long& acc,
                                     unsigned long long a,
                                     unsigned long long b) {
    asm("fma.rn.f32x2 %0, %1, %2, %0;" : "+l"(acc) : "l"(a), "l"(b));
}

// ---------------- in-degree histogram (edge_index is INT32) ----------------
__global__ void k_deg(const int* __restrict__ ei) {
    int e = blockIdx.x * blockDim.x + threadIdx.x;
    if (e < N_EDGES) atomicAdd(&g_hist[ei[N_EDGES + e]], 1);
}

// ---------------- scan pass 1 (+ fused dinv = rsqrt(deg+1)) ----------------
__global__ void k_scan1() {
    __shared__ int sh[SCAN_B];
    int t = threadIdx.x;
    int i = blockIdx.x * SCAN_B + t;
    int v = (i < N_NODES) ? g_hist[i] : 0;
    if (i < N_NODES) g_deg[i] = rsqrtf((float)v + 1.0f);
    sh[t] = v;
    __syncthreads();
    for (int off = 1; off < SCAN_B; off <<= 1) {
        int x = (t >= off) ? sh[t - off] : 0;
        __syncthreads();
        sh[t] += x;
        __syncthreads();
    }
    if (i < N_NODES) g_rowstart[i] = sh[t] - v;
    if (t == SCAN_B - 1) g_bsum[blockIdx.x] = sh[t];
}

// ---------------- scan pass 2+3 fused: block offsets + apply ----------------
__global__ void k_scan3() {
    __shared__ int sb[64];
    int t = threadIdx.x;
    if (t < 64) sb[t] = (t < N_SBLK) ? g_bsum[t] : 0;
    __syncthreads();
#pragma unroll
    for (int off = 1; off < 64; off <<= 1) {
        int x = (t < 64 && t >= off) ? sb[t - off] : 0;
        __syncthreads();
        if (t < 64) sb[t] += x;
        __syncthreads();
    }
    int i = blockIdx.x * blockDim.x + t;
    if (i < N_NODES) {
        int blk = i / SCAN_B;
        int add = blk ? sb[blk - 1] : 0;
        int rs = g_rowstart[i] + add;
        g_rowstart[i] = rs;
        g_cursor[i]   = rs;
    }
}

// ---------------- CSR fill ---------------------------------------------------
__global__ void k_fill(const int* __restrict__ ei) {
    int e = blockIdx.x * blockDim.x + threadIdx.x;
    if (e < N_EDGES) {
        int s = ei[e];
        int d = ei[N_EDGES + e];
        int pos = atomicAdd(&g_cursor[d], 1);
        g_csrc[pos] = s;
    }
}

// ---------------- transpose X [128,N] -> xT [N,128] ------------------------
__global__ void k_transpose(const float* __restrict__ X) {
    __shared__ float s[32][33];
    int n0 = blockIdx.x * 32;
    int f0 = blockIdx.y * 32;
    int tx = threadIdx.x, ty = threadIdx.y;          // (32, 8)
    int n = n0 + tx;
#pragma unroll
    for (int i = 0; i < 4; i++) {
        int f = f0 + ty + i * 8;
        if (n < N_NODES) s[ty + i * 8][tx] = X[(size_t)f * N_NODES + n];
    }
    __syncthreads();
#pragma unroll
    for (int i = 0; i < 4; i++) {
        int n2 = n0 + ty + i * 8;
        int f2 = f0 + tx;
        if (n2 < N_NODES) g_xT[(size_t)n2 * D + f2] = s[tx][ty + i * 8];
    }
}

// ---------------- GEMM (f32x2) ----------------------------------------------
// Layer 1 (src_sel=0): g_xw = A @ W          (raw; dinv applied in agg stage 0;
//                                             runs concurrent with CSR build)
// Layer 2 (src_sel=1): g_xw = (A @ W)*dinv   (pre-scaled fast path)
// Block: 128 nodes x 128 cols, 256 threads, 8 nodes x 8 cols per thread.
__global__ void __launch_bounds__(256) k_gemm(int src_sel,
                                              const float* __restrict__ W) {
    const float* __restrict__ A = src_sel ? g_f1 : g_xT;
    if (src_sel == 0 && blockIdx.x == 0 && threadIdx.x < D) {
        g_cs[threadIdx.x] = 0.0f;
        g_cs2[threadIdx.x] = 0.0f;
    }
    __shared__ float2 As2[128][16];    // 16 KB: (a,a) pairs, 16-col k-chunk
    __shared__ float  Ws[16][132];     // 8.25 KB padded
    int t  = threadIdx.x;
    int tx = t & 15;                   // column group (8 cols)
    int ty = t >> 4;                   // node group (8 nodes)
    int nbase = blockIdx.x * 128;

    unsigned long long acc[8][4];
#pragma unroll
    for (int i = 0; i < 8; i++)
#pragma unroll
        for (int p = 0; p < 4; p++) acc[i][p] = 0ull;

    for (int fc = 0; fc < D; fc += 16) {
#pragma unroll
        for (int k = 0; k < 8; k++) {           // 128x16 A chunk (dup pairs)
            int idx = t + k * 256;
            int r = idx >> 4, c = idx & 15;
            int n = nbase + r;
            float v = (n < N_NODES) ? A[(size_t)n * D + fc + c] : 0.0f;
            As2[r][c] = make_float2(v, v);
        }
#pragma unroll
        for (int k = 0; k < 8; k++) {           // 16x128 W chunk
            int idx = t + k * 256;
            int r = idx >> 7, c = idx & 127;
            Ws[r][c] = W[(fc + r) * D + c];
        }
        __syncthreads();
#pragma unroll
        for (int ff = 0; ff < 16; ff++) {
            const unsigned long long* wrow =
                (const unsigned long long*)&Ws[ff][tx * 8];
            unsigned long long w0 = wrow[0];
            unsigned long long w1 = wrow[1];
            unsigned long long w2 = wrow[2];
            unsigned long long w3 = wrow[3];
#pragma unroll
            for (int i = 0; i < 8; i++) {
                unsigned long long a2 =
                    *(const unsigned long long*)&As2[ty * 8 + i][ff];
                fma2(acc[i][0], a2, w0);
                fma2(acc[i][1], a2, w1);
                fma2(acc[i][2], a2, w2);
                fma2(acc[i][3], a2, w3);
            }
        }
        __syncthreads();
    }

#pragma unroll
    for (int i = 0; i < 8; i++) {
        int node = nbase + ty * 8 + i;
        if (node >= N_NODES) continue;
        float di = src_sel ? g_deg[node] : 1.0f;
        size_t off = (size_t)node * D + tx * 8;
        float2 p0 = *(float2*)&acc[i][0];
        float2 p1 = *(float2*)&acc[i][1];
        float2 p2 = *(float2*)&acc[i][2];
        float2 p3 = *(float2*)&acc[i][3];
        ((float4*)(g_xw + off))[0] =
            make_float4(p0.x * di, p0.y * di, p1.x * di, p1.y * di);
        ((float4*)(g_xw + off))[1] =
            make_float4(p2.x * di, p2.y * di, p3.x * di, p3.y * di);
    }
}

// ---------------- fused CSR gather + MessageNorm + GELU (+stats) -----------
// stage 0: xw raw   -> msg = dinv[d]*(dinv[d]*xw[d] + sum dinv[s]*xw[s]) + b
// stage 1: xw scaled-> msg = dinv[d]*(xw[d] + sum xw[s]) + b   (+res, +stats)
__global__ void __launch_bounds__(512) k_agg(int stage,
                                             const float* __restrict__ bias,
                                             const float* __restrict__ scale) {
    __shared__ float s_cs[D], s_cs2[D];
    if (stage) {
        if (threadIdx.x < D) { s_cs[threadIdx.x] = 0.0f; s_cs2[threadIdx.x] = 0.0f; }
        __syncthreads();
    }

    int gw = (blockIdx.x * blockDim.x + threadIdx.x) >> 5;
    int lane = threadIdx.x & 31;
    bool active = gw < N_NODES;
    float4 r = make_float4(0.f, 0.f, 0.f, 0.f);

    if (active) {
        const float4* xw4 = (const float4*)g_xw;
        float nd = g_deg[gw];
        float4 acc = xw4[(size_t)gw * 32 + lane];       // self-loop term
        if (!stage) { acc.x *= nd; acc.y *= nd; acc.z *= nd; acc.w *= nd; }
        int rs  = g_rowstart[gw];
        int end = rs + g_hist[gw];
        int e = rs;
        if (stage) {
            for (; e + 8 <= end; e += 8) {
                int s0 = g_csrc[e],     s1 = g_csrc[e + 1];
                int s2 = g_csrc[e + 2], s3 = g_csrc[e + 3];
                int s4 = g_csrc[e + 4], s5 = g_csrc[e + 5];
                int s6 = g_csrc[e + 6], s7 = g_csrc[e + 7];
                float4 v0 = xw4[(size_t)s0 * 32 + lane];
                float4 v1 = xw4[(size_t)s1 * 32 + lane];
                float4 v2 = xw4[(size_t)s2 * 32 + lane];
                float4 v3 = xw4[(size_t)s3 * 32 + lane];
                float4 v4 = xw4[(size_t)s4 * 32 + lane];
                float4 v5 = xw4[(size_t)s5 * 32 + lane];
                float4 v6 = xw4[(size_t)s6 * 32 + lane];
                float4 v7 = xw4[(size_t)s7 * 32 + lane];
                acc.x += ((v0.x + v1.x) + (v2.x + v3.x)) + ((v4.x + v5.x) + (v6.x + v7.x));
                acc.y += ((v0.y + v1.y) + (v2.y + v3.y)) + ((v4.y + v5.y) + (v6.y + v7.y));
                acc.z += ((v0.z + v1.z) + (v2.z + v3.z)) + ((v4.z + v5.z) + (v6.z + v7.z));
                acc.w += ((v0.w + v1.w) + (v2.w + v3.w)) + ((v4.w + v5.w) + (v6.w + v7.w));
            }
            for (; e < end; e++) {
                float4 v = xw4[(size_t)g_csrc[e] * 32 + lane];
                acc.x += v.x; acc.y += v.y; acc.z += v.z; acc.w += v.w;
            }
        } else {
            for (; e + 4 <= end; e += 4) {
                int s0 = g_csrc[e],     s1 = g_csrc[e + 1];
                int s2 = g_csrc[e + 2], s3 = g_csrc[e + 3];
                float n0 = g_deg[s0], n1 = g_deg[s1], n2 = g_deg[s2], n3 = g_deg[s3];
                float4 v0 = xw4[(size_t)s0 * 32 + lane];
                float4 v1 = xw4[(size_t)s1 * 32 + lane];
                float4 v2 = xw4[(size_t)s2 * 32 + lane];
                float4 v3 = xw4[(size_t)s3 * 32 + lane];
                acc.x += (v0.x*n0 + v1.x*n1) + (v2.x*n2 + v3.x*n3);
                acc.y += (v0.y*n0 + v1.y*n1) + (v2.y*n2 + v3.y*n3);
                acc.z += (v0.z*n0 + v1.z*n1) + (v2.z*n2 + v3.z*n3);
                acc.w += (v0.w*n0 + v1.w*n1) + (v2.w*n2 + v3.w*n3);
            }
            for (; e < end; e++) {
                int s0 = g_csrc[e];
                float n0 = g_deg[s0];
                float4 v = xw4[(size_t)s0 * 32 + lane];
                acc.x += v.x*n0; acc.y += v.y*n0; acc.z += v.z*n0; acc.w += v.w*n0;
            }
        }

        float4 bb = ((const float4*)bias)[lane];
        float4 m = make_float4(acc.x * nd + bb.x, acc.y * nd + bb.y,
                               acc.z * nd + bb.z, acc.w * nd + bb.w);

        size_t off = (size_t)gw * D;
        const float* xprev = stage ? g_f1 : g_xT;
        float4 xv = ((const float4*)(xprev + off))[lane];

        float ms = m.x*m.x + m.y*m.y + m.z*m.z + m.w*m.w;
        float xs = xv.x*xv.x + xv.y*xv.y + xv.z*xv.z + xv.w*xv.w;
#pragma unroll
        for (int o = 16; o; o >>= 1) {
            ms += __shfl_xor_sync(0xFFFFFFFFu, ms, o);
            xs += __shfl_xor_sync(0xFFFFFFFFu, xs, o);
        }
        float coef = scale[0] * sqrtf(xs) / fmaxf(sqrtf(ms), 1e-12f);

        r.x = gelu_exact(xv.x + coef * m.x);
        r.y = gelu_exact(xv.y + coef * m.y);
        r.z = gelu_exact(xv.z + coef * m.z);
        r.w = gelu_exact(xv.w + coef * m.w);

        if (stage) {
            float4 rv = ((const float4*)(g_xT + off))[lane];
            r.x += rv.x; r.y += rv.y; r.z += rv.z; r.w += rv.w;
        }
        float* out = stage ? g_y : g_f1;
        ((float4*)(out + off))[lane] = r;
    }

    if (stage) {
        if (active) {
            int c0 = lane * 4;
            atomicAdd(&s_cs [c0    ], r.x); atomicAdd(&s_cs2[c0    ], r.x * r.x);
            atomicAdd(&s_cs [c0 + 1], r.y); atomicAdd(&s_cs2[c0 + 1], r.y * r.y);
            atomicAdd(&s_cs [c0 + 2], r.z); atomicAdd(&s_cs2[c0 + 2], r.z * r.z);
            atomicAdd(&s_cs [c0 + 3], r.w); atomicAdd(&s_cs2[c0 + 3], r.w * r.w);
        }
        __syncthreads();
        if (threadIdx.x < D) {
            atomicAdd(&g_cs [threadIdx.x], s_cs [threadIdx.x]);
            atomicAdd(&g_cs2[threadIdx.x], s_cs2[threadIdx.x]);
        }
    }
}

// ---------------- finalize: GraphNorm + GELU (+ restore g_hist = 0) --------
__global__ void k_final(const float* __restrict__ gnw,
                        const float* __restrict__ gnb,
                        const float* __restrict__ gnm,
                        float* __restrict__ out) {
    const float invN = 1.0f / (float)N_NODES;
    for (int idx = blockIdx.x * blockDim.x + threadIdx.x;
         idx < N_NODES * D; idx += gridDim.x * blockDim.x) {
        if (idx < N_NODES) g_hist[idx] = 0;     // self-restore for next replay
        int c = idx & (D - 1);
        float mean = g_cs[c]  * invN;
        float ey2  = g_cs2[c] * invN;
        float msc  = gnm[c];
        float sub  = g_y[idx] - mean * msc;
        float var  = ey2 - 2.0f * msc * mean * mean + msc * msc * mean * mean;
        float o = gnw[c] * sub * rsqrtf(var + 1e-5f) + gnb[c];
        out[idx] = gelu_exact(o);
    }
}

// ---------------- launch ----------------------------------------------------
extern "C" void kernel_launch(void* const* d_in, const int* in_sizes, int n_in,
                              void* d_out, int out_size) {
    const float* X   = (const float*)d_in[0];
    const int*   ei  = (const int*)  d_in[1];     // int32 (JAX x64 disabled)
    const float* W1  = (const float*)d_in[2];
    const float* b1  = (const float*)d_in[3];
    const float* s1  = (const float*)d_in[4];
    const float* W2  = (const float*)d_in[5];
    const float* b2  = (const float*)d_in[6];
    const float* s2  = (const float*)d_in[7];
    const float* gnw = (const float*)d_in[8];
    const float* gnb = (const float*)d_in[9];
    const float* gnm = (const float*)d_in[10];
    float* out = (float*)d_out;

    const int TB = 256;
    int gemm_blocks = (N_NODES + 127) / 128;
    int agg_blocks  = (N_NODES * 32 + 511) / 512;
    dim3 tg((N_NODES + 31) / 32, D / 32);

    cudaStream_t se;                       // edge-pipeline branch
    cudaStreamCreateWithFlags(&se, cudaStreamNonBlocking);
    cudaEvent_t evFork, evJoin;
    cudaEventCreateWithFlags(&evFork, cudaEventDisableTiming);
    cudaEventCreateWithFlags(&evJoin, cudaEventDisableTiming);

    // fork: edge pipeline on se, dense pipeline on default stream
    cudaEventRecord(evFork, 0);
    cudaStreamWaitEvent(se, evFork, 0);

    // branch A (se): CSR build + dinv
    k_deg   <<<(N_EDGES + TB - 1) / TB, TB, 0, se>>>(ei);
    k_scan1 <<<N_SBLK, SCAN_B, 0, se>>>();
    k_scan3 <<<(N_NODES + TB - 1) / TB, TB, 0, se>>>();
    k_fill  <<<(N_EDGES + TB - 1) / TB, TB, 0, se>>>(ei);
    cudaEventRecord(evJoin, se);

    // branch B (default): transpose + raw GEMM layer 1
    k_transpose<<<tg, dim3(32, 8)>>>(X);
    k_gemm <<<gemm_blocks, TB>>>(0, W1);

    // join
    cudaStreamWaitEvent(0, evJoin, 0);

    // ---- layer 1 aggregation (applies dinv per edge) ----
    k_agg  <<<agg_blocks, 512>>>(0, b1, s1);

    // ---- layer 2 (pre-scaled path) ----
    k_gemm <<<gemm_blocks, TB>>>(1, W2);
    k_agg  <<<agg_blocks, 512>>>(1, b2, s2);

    // ---- GraphNorm + GELU ----
    k_final<<<4096, TB>>>(gnw, gnb, gnm, out);

    cudaEventDestroy(evFork);
    cudaEventDestroy(evJoin);
    cudaStreamDestroy(se);
}